// round 8
// baseline (speedup 1.0000x reference)
#include <cuda_runtime.h>
#include <cuda_fp16.h>
#include <math.h>

#define NN 100000
#define NE 800000
#define NG 2048
#define NB 196          // ceil(NN/512) scan blocks
#define CAP 160         // max nodes per graph handled in k_read smem
#define AST 392         // halves per A-panel row (384 + 8 pad)

typedef unsigned int uint;

// ---------------- scratch (device globals; no runtime allocation) ----------------
__device__ float g_h[NN*64];
__device__ float g_h2[NN*64];
__device__ float g_Wc[384*64];              // rows 0..319: W_r; 320..383: root
__device__ __half g_Bfh[64*384];            // B^T hi fp16: [n][k]
__device__ __half g_Bfl[64*384];            // B^T lo fp16
__device__ float g_invcnt[NN];
__device__ int   g_cnt[NN];
__device__ int   g_rowptr[NN+1];
__device__ int   g_bsum[NB];
__device__ int   g_fill[NN];
__device__ int   g_eidx[NE];                // packed: src | (rel<<20)
__device__ int   g_gstart[NG+1];
__device__ float g_Wl[192*256];
__device__ float g_bl[256];
__device__ float g_qstar[NG*128];
__device__ float g_hx[NG*64];
__device__ float g_cx[NG*64];
__device__ float g_gates[NG*256];
__device__ float g_out1[NG*64];

// ---------------- prep kernels ----------------
__global__ void k_wc(const float* __restrict__ att, const float* __restrict__ basis,
                     const float* __restrict__ root){
  int k = blockIdx.x, e = threadIdx.x;
  float s;
  if (k < 320){
    int r = k >> 6, d = k & 63;
    s = 0.f;
    #pragma unroll
    for (int b = 0; b < 5; b++) s += att[r*5+b] * basis[(b*64+d)*64+e];
  } else {
    s = root[(k-320)*64 + e];
  }
  g_Wc[k*64+e] = s;
}

__global__ void k_wb(){
  int k = blockIdx.x, n = threadIdx.x;
  float v = g_Wc[k*64+n];
  __half hi = __float2half_rn(v);
  __half lo = __float2half_rn(v - __half2float(hi));
  g_Bfh[n*384+k] = hi;
  g_Bfl[n*384+k] = lo;
}

// 4 nodes per 256-thread block
__global__ void __launch_bounds__(256) k_h0(const float* __restrict__ x,
                                            const float* __restrict__ w,
                                            const float* __restrict__ b){
  __shared__ float sx[4][15];
  int tid = threadIdx.x;
  int local = tid >> 6, e = tid & 63;
  int n = blockIdx.x*4 + local;
  if (e < 15 && n < NN) sx[local][e] = x[n*15+e];
  __syncthreads();
  if (n >= NN) return;
  float s = b[e];
  #pragma unroll
  for (int i = 0; i < 15; i++) s += sx[local][i]*w[i*64+e];
  g_h[(size_t)n*64+e] = fmaxf(s, 0.f);
}

__global__ void k_hist(const int* __restrict__ dst){
  int e = blockIdx.x*blockDim.x + threadIdx.x;
  if (e < NE) atomicAdd(&g_cnt[dst[e]], 1);
}

__global__ void k_scan1(){
  __shared__ int sm[512];
  int b = blockIdx.x, t = threadIdx.x;
  int i = b*512 + t;
  sm[t] = (i < NN) ? g_cnt[i] : 0;
  __syncthreads();
  for (int o = 256; o; o >>= 1){
    if (t < o) sm[t] += sm[t+o];
    __syncthreads();
  }
  if (t == 0) g_bsum[b] = sm[0];
}

__global__ void k_scan2(){
  if (threadIdx.x == 0){
    int acc = 0;
    for (int b = 0; b < NB; b++){ int v = g_bsum[b]; g_bsum[b] = acc; acc += v; }
    g_rowptr[NN] = NE;
  }
}

__global__ void k_scan3(){
  __shared__ int sm[512];
  int b = blockIdx.x, t = threadIdx.x;
  int i = b*512 + t;
  int v = (i < NN) ? g_cnt[i] : 0;
  sm[t] = v;
  __syncthreads();
  for (int o = 1; o < 512; o <<= 1){
    int add = (t >= o) ? sm[t-o] : 0;
    __syncthreads();
    sm[t] += add;
    __syncthreads();
  }
  if (i < NN) g_rowptr[i] = g_bsum[b] + sm[t] - v;
}

__global__ void k_scatter(const int* __restrict__ ei, const int* __restrict__ et){
  int e = blockIdx.x*blockDim.x + threadIdx.x;
  if (e >= NE) return;
  int src = ei[e];
  int dst = ei[NE + e];
  int rel = et[e];
  int pos = g_rowptr[dst] + atomicAdd(&g_fill[dst], 1);
  g_eidx[pos] = src | (rel << 20);
}

__global__ void k_invc(){
  int n = blockIdx.x*blockDim.x + threadIdx.x;
  if (n < NN) g_invcnt[n] = 1.0f / fmaxf((float)g_cnt[n], 1.0f);
}

__global__ void k_gstart(const int* __restrict__ batch){
  int g = blockIdx.x*blockDim.x + threadIdx.x;
  if (g > NG) return;
  int lo = 0, hi = NN;
  while (lo < hi){ int mid = (lo+hi) >> 1; if (batch[mid] < g) lo = mid+1; else hi = mid; }
  g_gstart[g] = lo;
}

__global__ void k_wl(const float* __restrict__ w_ih, const float* __restrict__ w_hh,
                     const float* __restrict__ b_ih, const float* __restrict__ b_hh){
  int k = blockIdx.x, j = threadIdx.x;
  g_Wl[k*256+j] = (k < 128) ? w_ih[j*128+k] : w_hh[j*64 + (k-128)];
  if (k == 0) g_bl[j] = b_ih[j] + b_hh[j];
}

// ---------------- fused RGCN step ----------------
// Phase 1: warp-per-node register CSR aggregation -> fp16 A panel in smem (64 x 384 + root).
// Phase 2: 64x384 @ 384x64 fp16 MMA, B 2-term split.  59 KB smem -> 3 blocks/SM.
#define MMA_F16(d, a, b0v, b1v) \
  asm volatile("mma.sync.aligned.m16n8k16.row.col.f32.f16.f16.f32 " \
      "{%0,%1,%2,%3}, {%4,%5,%6,%7}, {%8,%9}, {%0,%1,%2,%3};" \
      : "+f"(d[0]), "+f"(d[1]), "+f"(d[2]), "+f"(d[3]) \
      : "r"(a[0]), "r"(a[1]), "r"(a[2]), "r"(a[3]), "r"(b0v), "r"(b1v))

__global__ void __launch_bounds__(256, 3) k_prop(const float* __restrict__ hin,
                                                 float* __restrict__ hout,
                                                 const float* __restrict__ cb){
  extern __shared__ __half smem[];
  __half* Ah = smem;                       // [64][AST]
  __half* Bh = Ah + 64*AST;                // [64][40]
  __half* Bl = Bh + 64*40;                 // [64][40]

  int tid = threadIdx.x, lane = tid & 31, w = tid >> 5;
  int m0 = blockIdx.x * 64;

  // -------- phase 1: aggregate into fp16 smem panel --------
  #pragma unroll 1
  for (int i = 0; i < 8; i++){
    int row = w*8 + i;
    int n = m0 + row;
    __half* ar = Ah + row*AST + 2*lane;
    if (n < NN){
      float ac[5][2] = {};
      int rp0 = g_rowptr[n], rp1 = g_rowptr[n+1];
      int e = rp0;
      for (; e + 2 <= rp1; e += 2){
        int p0 = g_eidx[e], p1 = g_eidx[e+1];
        float2 x = *(const float2*)(hin + (size_t)(p0 & 0xFFFFF)*64 + 2*lane);
        float2 y = *(const float2*)(hin + (size_t)(p1 & 0xFFFFF)*64 + 2*lane);
        int r0 = p0 >> 20, r1 = p1 >> 20;
        #pragma unroll
        for (int r = 0; r < 5; r++){
          if (r0 == r){ ac[r][0] += x.x; ac[r][1] += x.y; }
          if (r1 == r){ ac[r][0] += y.x; ac[r][1] += y.y; }
        }
      }
      if (e < rp1){
        int p0 = g_eidx[e];
        float2 x = *(const float2*)(hin + (size_t)(p0 & 0xFFFFF)*64 + 2*lane);
        int r0 = p0 >> 20;
        #pragma unroll
        for (int r = 0; r < 5; r++)
          if (r0 == r){ ac[r][0] += x.x; ac[r][1] += x.y; }
      }
      float ic = g_invcnt[n];
      #pragma unroll
      for (int r = 0; r < 5; r++){
        float2 v = { ac[r][0]*ic, ac[r][1]*ic };
        *(__half2*)(ar + r*64) = __float22half2_rn(v);
      }
      float2 hv = *(const float2*)(hin + (size_t)n*64 + 2*lane);
      *(__half2*)(ar + 320) = __float22half2_rn(hv);
    } else {
      __half2 z = __float22half2_rn({0.f, 0.f});
      #pragma unroll
      for (int r = 0; r < 6; r++) *(__half2*)(ar + r*64) = z;
    }
  }
  __syncthreads();

  // -------- phase 2: MMA --------
  int wrow = (w >> 1) * 16;
  int wcol = (w & 1) * 32;
  int r = lane >> 2;            // 0..7
  int q2 = (lane & 3) * 2;      // 0,2,4,6

  float acc[4][4];
  #pragma unroll
  for (int nt = 0; nt < 4; nt++)
    #pragma unroll
    for (int j = 0; j < 4; j++) acc[nt][j] = 0.f;

  int sn = tid >> 2, sbs = (tid & 3) * 8;     // B staging: 8 halves per thread

  for (int cc = 0; cc < 12; cc++){
    int k0 = cc * 32;
    *(uint4*)(Bh + sn*40 + sbs) = *(const uint4*)(g_Bfh + sn*384 + k0 + sbs);
    *(uint4*)(Bl + sn*40 + sbs) = *(const uint4*)(g_Bfl + sn*384 + k0 + sbs);
    __syncthreads();
    #pragma unroll
    for (int s = 0; s < 2; s++){
      int ks = k0 + s*16;
      int bks = s*16;
      uint ah[4];
      ah[0] = *(const uint*)(Ah + (wrow + r    )*AST + ks + q2);
      ah[1] = *(const uint*)(Ah + (wrow + r + 8)*AST + ks + q2);
      ah[2] = *(const uint*)(Ah + (wrow + r    )*AST + ks + q2 + 8);
      ah[3] = *(const uint*)(Ah + (wrow + r + 8)*AST + ks + q2 + 8);
      #pragma unroll
      for (int nt = 0; nt < 4; nt++){
        int nn = wcol + nt*8 + r;
        uint bh0 = *(const uint*)(Bh + nn*40 + bks + q2);
        uint bh1 = *(const uint*)(Bh + nn*40 + bks + q2 + 8);
        uint bl0 = *(const uint*)(Bl + nn*40 + bks + q2);
        uint bl1 = *(const uint*)(Bl + nn*40 + bks + q2 + 8);
        MMA_F16(acc[nt], ah, bh0, bh1);
        MMA_F16(acc[nt], ah, bl0, bl1);
      }
    }
    __syncthreads();
  }

  // epilogue: relu(acc + bias)
  int row0 = m0 + wrow + r;
  #pragma unroll
  for (int nt = 0; nt < 4; nt++){
    int col = wcol + nt*8 + q2;
    float b0v = cb[col], b1v = cb[col+1];
    if (row0 < NN){
      float2 o = { fmaxf(acc[nt][0] + b0v, 0.f), fmaxf(acc[nt][1] + b1v, 0.f) };
      *(float2*)(hout + (size_t)row0*64 + col) = o;
    }
    if (row0 + 8 < NN){
      float2 o = { fmaxf(acc[nt][2] + b0v, 0.f), fmaxf(acc[nt][3] + b1v, 0.f) };
      *(float2*)(hout + (size_t)(row0+8)*64 + col) = o;
    }
  }
}

// ---------------- Set2Set ----------------
__global__ void __launch_bounds__(256) k_gates(){
  __shared__ float Asg[64][36];
  __shared__ float Bsg[32][64];
  int tid = threadIdx.x;
  int tx = tid & 15, ty = tid >> 4;
  int m0 = blockIdx.x * 64;
  int n0 = blockIdx.y * 64;
  int lrow = tid >> 2;
  int lk = (tid & 3) * 8;
  int grow = m0 + lrow;
  int bk = tid >> 3, be = (tid & 7) * 8;
  float acc[4][4] = {};
  for (int kk = 0; kk < 6; kk++){
    int kb = kk * 32;
    float4 a0, a1;
    if (kk < 4){
      const float* p = g_qstar + grow*128 + kb + lk;
      a0 = *(const float4*)p; a1 = *(const float4*)(p+4);
    } else {
      const float* p = g_hx + grow*64 + (kb - 128) + lk;
      a0 = *(const float4*)p; a1 = *(const float4*)(p+4);
    }
    const float* wp = g_Wl + (kb + bk)*256 + n0 + be;
    float4 b0 = *(const float4*)wp;
    float4 b1 = *(const float4*)(wp+4);
    __syncthreads();
    *(float4*)&Asg[lrow][lk]   = a0;
    *(float4*)&Asg[lrow][lk+4] = a1;
    *(float4*)&Bsg[bk][be]     = b0;
    *(float4*)&Bsg[bk][be+4]   = b1;
    __syncthreads();
    #pragma unroll
    for (int k = 0; k < 32; k++){
      float4 bv = *(float4*)&Bsg[k][tx*4];
      #pragma unroll
      for (int i = 0; i < 4; i++){
        float av = Asg[ty*4+i][k];
        acc[i][0] += av*bv.x;
        acc[i][1] += av*bv.y;
        acc[i][2] += av*bv.z;
        acc[i][3] += av*bv.w;
      }
    }
  }
  #pragma unroll
  for (int i = 0; i < 4; i++){
    int m = m0 + ty*4 + i;
    float* op = g_gates + m*256 + n0 + tx*4;
    op[0] = acc[i][0] + g_bl[n0 + tx*4 + 0];
    op[1] = acc[i][1] + g_bl[n0 + tx*4 + 1];
    op[2] = acc[i][2] + g_bl[n0 + tx*4 + 2];
    op[3] = acc[i][3] + g_bl[n0 + tx*4 + 3];
  }
}

__device__ __forceinline__ float sigf(float v){ return 1.0f/(1.0f + expf(-v)); }

// fused LSTM update + softmax readout. Block per graph, 128 threads.
__global__ void __launch_bounds__(128) k_read(const float* __restrict__ h){
  __shared__ float se[CAP];
  __shared__ float shx[64];
  __shared__ float red[2];
  int g = blockIdx.x;
  int tid = threadIdx.x, lane = tid & 31, w = tid >> 5;
  int s0 = g_gstart[g];
  int cnt = g_gstart[g+1] - s0;
  if (cnt > CAP) cnt = CAP;
  // LSTM update (threads 0..63)
  if (tid < 64){
    const float* ga = g_gates + g*256;
    float iv = sigf(ga[tid]);
    float fv = sigf(ga[64+tid]);
    float gv = tanhf(ga[128+tid]);
    float ov = sigf(ga[192+tid]);
    float c = fv * g_cx[g*64+tid] + iv * gv;
    float hx = ov * tanhf(c);
    g_cx[g*64+tid] = c;
    g_hx[g*64+tid] = hx;
    shx[tid] = hx;
  }
  __syncthreads();
  // e per node
  for (int i = w; i < cnt; i += 4){
    const float* hr = h + (size_t)(s0+i)*64;
    float s = hr[lane]*shx[lane] + hr[lane+32]*shx[lane+32];
    #pragma unroll
    for (int o = 16; o; o >>= 1) s += __shfl_xor_sync(0xffffffffu, s, o);
    if (lane == 0) se[i] = s;
  }
  __syncthreads();
  if (tid < 32){
    float m = -3.0e38f;
    for (int i = lane; i < cnt; i += 32) m = fmaxf(m, se[i]);
    #pragma unroll
    for (int o = 16; o; o >>= 1) m = fmaxf(m, __shfl_xor_sync(0xffffffffu, m, o));
    if (lane == 0) red[0] = m;
  }
  __syncthreads();
  float m = red[0];
  for (int i = tid; i < cnt; i += 128) se[i] = expf(se[i] - m);
  __syncthreads();
  if (tid < 32){
    float s = 0.f;
    for (int i = lane; i < cnt; i += 32) s += se[i];
    #pragma unroll
    for (int o = 16; o; o >>= 1) s += __shfl_xor_sync(0xffffffffu, s, o);
    if (lane == 0) red[1] = s;
  }
  __syncthreads();
  float ssum = red[1];
  if (tid < 64){
    float r = 0.f;
    #pragma unroll 4
    for (int i = 0; i < cnt; i++) r += se[i] * h[(size_t)(s0+i)*64 + tid];
    g_qstar[g*128 + tid]      = shx[tid];
    g_qstar[g*128 + 64 + tid] = (ssum > 0.f) ? (r / ssum) : 0.f;
  }
}

// ---------------- head ----------------
__global__ void k_lin1(const float* __restrict__ w, const float* __restrict__ b){
  int t = blockIdx.x*blockDim.x + threadIdx.x;
  if (t >= NG*64) return;
  int g = t >> 6, e = t & 63;
  float s = b[e];
  const float* q = g_qstar + g*128;
  #pragma unroll 8
  for (int k = 0; k < 128; k++) s += q[k]*w[k*64+e];
  g_out1[t] = fmaxf(s, 0.f);
}

__global__ void k_lin2(const float* __restrict__ w, const float* __restrict__ b,
                       float* __restrict__ out){
  int t = blockIdx.x*blockDim.x + threadIdx.x;
  if (t >= NG*12) return;
  int g = t / 12, j = t % 12;
  float s = b[j];
  const float* o1 = g_out1 + g*64;
  #pragma unroll 8
  for (int d = 0; d < 64; d++) s += o1[d]*w[d*12+j];
  out[t] = s;
}

// ---------------- launch ----------------
extern "C" void kernel_launch(void* const* d_in, const int* in_sizes, int n_in,
                              void* d_out, int out_size){
  const float* x      = (const float*)d_in[0];
  const int*   ei     = (const int*)  d_in[1];
  const int*   et     = (const int*)  d_in[2];
  const int*   batch  = (const int*)  d_in[3];
  const float* lin0_w = (const float*)d_in[4];
  const float* lin0_b = (const float*)d_in[5];
  const float* basis  = (const float*)d_in[6];
  const float* att    = (const float*)d_in[7];
  const float* root   = (const float*)d_in[8];
  const float* conv_b = (const float*)d_in[9];
  const float* w_ih   = (const float*)d_in[10];
  const float* w_hh   = (const float*)d_in[11];
  const float* b_ih   = (const float*)d_in[12];
  const float* b_hh   = (const float*)d_in[13];
  const float* lin1_w = (const float*)d_in[14];
  const float* lin1_b = (const float*)d_in[15];
  const float* lin2_w = (const float*)d_in[16];
  const float* lin2_b = (const float*)d_in[17];
  float* out = (float*)d_out;

  void *p_cnt=0, *p_fill=0, *p_qs=0, *p_hx=0, *p_cx=0, *p_h=0, *p_h2=0;
  cudaGetSymbolAddress(&p_cnt,  g_cnt);
  cudaGetSymbolAddress(&p_fill, g_fill);
  cudaGetSymbolAddress(&p_qs,   g_qstar);
  cudaGetSymbolAddress(&p_hx,   g_hx);
  cudaGetSymbolAddress(&p_cx,   g_cx);
  cudaGetSymbolAddress(&p_h,    g_h);
  cudaGetSymbolAddress(&p_h2,   g_h2);

  const int PROP_SMEM = (64*AST + 2*64*40) * (int)sizeof(__half);
  cudaFuncSetAttribute(k_prop, cudaFuncAttributeMaxDynamicSharedMemorySize, PROP_SMEM);

  // prologue: weights, h0, CSR build, graph offsets
  k_wc<<<384, 64>>>(att, basis, root);
  k_wb<<<384, 64>>>();
  k_h0<<<(NN+3)/4, 256>>>(x, lin0_w, lin0_b);
  cudaMemsetAsync(p_cnt, 0, NN*sizeof(int));
  cudaMemsetAsync(p_fill, 0, NN*sizeof(int));
  k_hist<<<(NE+255)/256, 256>>>(ei + NE);
  k_scan1<<<NB, 512>>>();
  k_scan2<<<1, 32>>>();
  k_scan3<<<NB, 512>>>();
  k_scatter<<<(NE+255)/256, 256>>>(ei, et);
  k_invc<<<(NN+255)/256, 256>>>();
  k_gstart<<<(NG+256)/256, 256>>>(batch);
  k_wl<<<192, 256>>>(w_ih, w_hh, b_ih, b_hh);
  cudaMemsetAsync(p_qs, 0, NG*128*sizeof(float));
  cudaMemsetAsync(p_hx, 0, NG*64*sizeof(float));
  cudaMemsetAsync(p_cx, 0, NG*64*sizeof(float));

  // RGCN propagation: fully fused per step (fp16 panel in smem)
  float* hA = (float*)p_h;
  float* hB = (float*)p_h2;
  for (int s = 0; s < 6; s++){
    k_prop<<<(NN+63)/64, 256, PROP_SMEM>>>(hA, hB, conv_b);
    float* tmp = hA; hA = hB; hB = tmp;
  }

  // Set2Set: gates GEMM + fused(update, softmax readout)
  for (int t = 0; t < 6; t++){
    k_gates<<<dim3(NG/64, 4), 256>>>();
    k_read<<<NG, 128>>>(hA);
  }

  // head
  k_lin1<<<(NG*64+255)/256, 256>>>(lin1_w, lin1_b);
  k_lin2<<<(NG*12+255)/256, 256>>>(lin2_w, lin2_b, out);
}

// round 9
// speedup vs baseline: 1.1365x; 1.1365x over previous
#include <cuda_runtime.h>
#include <cuda_fp16.h>
#include <math.h>

#define NN 100000
#define NNP 100096      // 782 * 128 (panel M padded to gemm tile; pad rows stay zero)
#define NE 800000
#define NG 2048
#define NB 196          // ceil(NN/512) scan blocks
#define CAP 160         // max nodes per graph handled in k_read smem

typedef unsigned int uint;

// ---------------- scratch (device globals; no runtime allocation) ----------------
__device__ __half g_hh[NN*64];              // node features fp16 (ping)
__device__ __half g_hh2[NN*64];             // node features fp16 (pong)
__device__ float g_Wc[384*64];              // rows 0..319: W_r; 320..383: root
__device__ __half g_Af[(size_t)NNP*320];    // fp16 aggregation panel (pad rows zero)
__device__ __half g_Bfh[64*384];            // B^T hi fp16: [n][k]
__device__ __half g_Bfl[64*384];            // B^T lo fp16
__device__ float g_invcnt[NN];
__device__ int   g_cnt[NN];
__device__ int   g_rowptr[NN+1];
__device__ int   g_bsum[NB];
__device__ int   g_fill[NN];
__device__ int   g_eidx[NE];                // packed: src | (rel<<20)
__device__ int   g_gstart[NG+1];
__device__ float g_Wl[192*256];
__device__ float g_bl[256];
__device__ float g_qstar[NG*128];
__device__ float g_hx[NG*64];
__device__ float g_cx[NG*64];
__device__ float g_gates[NG*256];
__device__ float g_out1[NG*64];

// ---------------- prep kernels ----------------
__global__ void k_wc(const float* __restrict__ att, const float* __restrict__ basis,
                     const float* __restrict__ root){
  int k = blockIdx.x, e = threadIdx.x;
  float s;
  if (k < 320){
    int r = k >> 6, d = k & 63;
    s = 0.f;
    #pragma unroll
    for (int b = 0; b < 5; b++) s += att[r*5+b] * basis[(b*64+d)*64+e];
  } else {
    s = root[(k-320)*64 + e];
  }
  g_Wc[k*64+e] = s;
}

__global__ void k_wb(){
  int k = blockIdx.x, n = threadIdx.x;
  float v = g_Wc[k*64+n];
  __half hi = __float2half_rn(v);
  __half lo = __float2half_rn(v - __half2float(hi));
  g_Bfh[n*384+k] = hi;
  g_Bfl[n*384+k] = lo;
}

// 4 nodes per 256-thread block; writes fp16 h0
__global__ void __launch_bounds__(256) k_h0(const float* __restrict__ x,
                                            const float* __restrict__ w,
                                            const float* __restrict__ b){
  __shared__ float sx[4][15];
  int tid = threadIdx.x;
  int local = tid >> 6, e = tid & 63;
  int n = blockIdx.x*4 + local;
  if (e < 15 && n < NN) sx[local][e] = x[n*15+e];
  __syncthreads();
  if (n >= NN) return;
  float s = b[e];
  #pragma unroll
  for (int i = 0; i < 15; i++) s += sx[local][i]*w[i*64+e];
  g_hh[(size_t)n*64+e] = __float2half_rn(fmaxf(s, 0.f));
}

__global__ void k_hist(const int* __restrict__ dst){
  int e = blockIdx.x*blockDim.x + threadIdx.x;
  if (e < NE) atomicAdd(&g_cnt[dst[e]], 1);
}

__global__ void k_scan1(){
  __shared__ int sm[512];
  int b = blockIdx.x, t = threadIdx.x;
  int i = b*512 + t;
  sm[t] = (i < NN) ? g_cnt[i] : 0;
  __syncthreads();
  for (int o = 256; o; o >>= 1){
    if (t < o) sm[t] += sm[t+o];
    __syncthreads();
  }
  if (t == 0) g_bsum[b] = sm[0];
}

__global__ void k_scan2(){
  if (threadIdx.x == 0){
    int acc = 0;
    for (int b = 0; b < NB; b++){ int v = g_bsum[b]; g_bsum[b] = acc; acc += v; }
    g_rowptr[NN] = NE;
  }
}

__global__ void k_scan3(){
  __shared__ int sm[512];
  int b = blockIdx.x, t = threadIdx.x;
  int i = b*512 + t;
  int v = (i < NN) ? g_cnt[i] : 0;
  sm[t] = v;
  __syncthreads();
  for (int o = 1; o < 512; o <<= 1){
    int add = (t >= o) ? sm[t-o] : 0;
    __syncthreads();
    sm[t] += add;
    __syncthreads();
  }
  if (i < NN) g_rowptr[i] = g_bsum[b] + sm[t] - v;
}

__global__ void k_scatter(const int* __restrict__ ei, const int* __restrict__ et){
  int e = blockIdx.x*blockDim.x + threadIdx.x;
  if (e >= NE) return;
  int src = ei[e];
  int dst = ei[NE + e];
  int rel = et[e];
  int pos = g_rowptr[dst] + atomicAdd(&g_fill[dst], 1);
  g_eidx[pos] = src | (rel << 20);
}

__global__ void k_invc(){
  int n = blockIdx.x*blockDim.x + threadIdx.x;
  if (n < NN) g_invcnt[n] = 1.0f / fmaxf((float)g_cnt[n], 1.0f);
}

__global__ void k_gstart(const int* __restrict__ batch){
  int g = blockIdx.x*blockDim.x + threadIdx.x;
  if (g > NG) return;
  int lo = 0, hi = NN;
  while (lo < hi){ int mid = (lo+hi) >> 1; if (batch[mid] < g) lo = mid+1; else hi = mid; }
  g_gstart[g] = lo;
}

__global__ void k_wl(const float* __restrict__ w_ih, const float* __restrict__ w_hh,
                     const float* __restrict__ b_ih, const float* __restrict__ b_hh){
  int k = blockIdx.x, j = threadIdx.x;
  g_Wl[k*256+j] = (k < 128) ? w_ih[j*128+k] : w_hh[j*64 + (k-128)];
  if (k == 0) g_bl[j] = b_ih[j] + b_hh[j];
}

// ---------------- aggregation: warp-per-node CSR over fp16 h -> fp16 panel ----------------
__global__ void __launch_bounds__(256) k_agg(const __half* __restrict__ hin){
  int n = (blockIdx.x*blockDim.x + threadIdx.x) >> 5;   // warp per node; grid exact
  int lane = threadIdx.x & 31;
  float ac[5][2] = {};
  int rp0 = g_rowptr[n], rp1 = g_rowptr[n+1];
  int e = rp0;
  for (; e + 2 <= rp1; e += 2){
    int p0 = g_eidx[e], p1 = g_eidx[e+1];
    float2 x = __half22float2(*(const __half2*)(hin + (size_t)(p0 & 0xFFFFF)*64 + 2*lane));
    float2 y = __half22float2(*(const __half2*)(hin + (size_t)(p1 & 0xFFFFF)*64 + 2*lane));
    int r0 = p0 >> 20, r1 = p1 >> 20;
    #pragma unroll
    for (int r = 0; r < 5; r++){
      if (r0 == r){ ac[r][0] += x.x; ac[r][1] += x.y; }
      if (r1 == r){ ac[r][0] += y.x; ac[r][1] += y.y; }
    }
  }
  if (e < rp1){
    int p0 = g_eidx[e];
    float2 x = __half22float2(*(const __half2*)(hin + (size_t)(p0 & 0xFFFFF)*64 + 2*lane));
    int r0 = p0 >> 20;
    #pragma unroll
    for (int r = 0; r < 5; r++)
      if (r0 == r){ ac[r][0] += x.x; ac[r][1] += x.y; }
  }
  float ic = g_invcnt[n];
  size_t base = (size_t)n*320 + 2*lane;
  #pragma unroll
  for (int r = 0; r < 5; r++){
    float2 v = { ac[r][0]*ic, ac[r][1]*ic };
    *(__half2*)(g_Af + base + r*64) = __float22half2_rn(v);
  }
}

// ---------------- GEMM: [NNP x 384] @ [384 x 64] fp16 MMA, B 2-term, reg-pipelined ----------------
#define MMA_F16(d, a, b0v, b1v) \
  asm volatile("mma.sync.aligned.m16n8k16.row.col.f32.f16.f16.f32 " \
      "{%0,%1,%2,%3}, {%4,%5,%6,%7}, {%8,%9}, {%0,%1,%2,%3};" \
      : "+f"(d[0]), "+f"(d[1]), "+f"(d[2]), "+f"(d[3]) \
      : "r"(a[0]), "r"(a[1]), "r"(a[2]), "r"(a[3]), "r"(b0v), "r"(b1v))

__global__ void __launch_bounds__(256) k_gemm(const __half* __restrict__ hin,
                                              __half* __restrict__ hout,
                                              const float* __restrict__ cb){
  __shared__ __half Ah_s[128][40];
  __shared__ __half Bh_s[64][40];
  __shared__ __half Bl_s[64][40];
  int tid = threadIdx.x, lane = tid & 31, w = tid >> 5;
  int m0 = blockIdx.x * 128;
  int wrow = w * 16;
  int r = lane >> 2;            // 0..7
  int q2 = (lane & 3) * 2;      // 0,2,4,6

  float acc[8][4];
  #pragma unroll
  for (int nt = 0; nt < 8; nt++)
    #pragma unroll
    for (int j = 0; j < 4; j++) acc[nt][j] = 0.f;

  int srow = tid >> 1, sseg = (tid & 1) * 16;    // A staging: 16 halves per thread
  int sn = tid >> 2,  sbs = (tid & 3) * 8;       // B staging: 8 halves per thread
  int rw = m0 + srow; if (rw >= NN) rw = NN - 1;
  const __half* hrow = hin + (size_t)rw*64;

  uint4 pf0, pf1, pf2, pf3;
  auto LD = [&](int cc){
    const __half* pa = (cc < 10)
        ? g_Af + (size_t)(m0 + srow)*320 + cc*32 + sseg
        : hrow + (cc - 10)*32 + sseg;
    pf0 = *(const uint4*)pa;
    pf1 = *(const uint4*)(pa + 8);
    pf2 = *(const uint4*)(g_Bfh + sn*384 + cc*32 + sbs);
    pf3 = *(const uint4*)(g_Bfl + sn*384 + cc*32 + sbs);
  };
  auto ST = [&](){
    *(uint4*)&Ah_s[srow][sseg]     = pf0;
    *(uint4*)&Ah_s[srow][sseg + 8] = pf1;
    *(uint4*)&Bh_s[sn][sbs] = pf2;
    *(uint4*)&Bl_s[sn][sbs] = pf3;
  };

  LD(0); ST();
  __syncthreads();

  for (int cc = 0; cc < 12; cc++){
    if (cc < 11) LD(cc + 1);            // prefetch next chunk while computing
    #pragma unroll
    for (int s = 0; s < 2; s++){
      int ks = s * 16;
      uint ah[4];
      ah[0] = *(const uint*)&Ah_s[wrow + r    ][ks + q2];
      ah[1] = *(const uint*)&Ah_s[wrow + r + 8][ks + q2];
      ah[2] = *(const uint*)&Ah_s[wrow + r    ][ks + q2 + 8];
      ah[3] = *(const uint*)&Ah_s[wrow + r + 8][ks + q2 + 8];
      #pragma unroll
      for (int nt = 0; nt < 8; nt++){
        int nn = nt*8 + r;
        uint bh0 = *(const uint*)&Bh_s[nn][ks + q2];
        uint bh1 = *(const uint*)&Bh_s[nn][ks + q2 + 8];
        uint bl0 = *(const uint*)&Bl_s[nn][ks + q2];
        uint bl1 = *(const uint*)&Bl_s[nn][ks + q2 + 8];
        MMA_F16(acc[nt], ah, bh0, bh1);
        MMA_F16(acc[nt], ah, bl0, bl1);
      }
    }
    __syncthreads();
    if (cc < 11){
      ST();
      __syncthreads();
    }
  }

  // epilogue: relu(acc + bias) -> fp16 h
  int row0 = m0 + wrow + r;
  #pragma unroll
  for (int nt = 0; nt < 8; nt++){
    int col = nt*8 + q2;
    float b0v = cb[col], b1v = cb[col+1];
    if (row0 < NN){
      *(__half2*)(hout + (size_t)row0*64 + col) =
        __floats2half2_rn(fmaxf(acc[nt][0] + b0v, 0.f), fmaxf(acc[nt][1] + b1v, 0.f));
    }
    if (row0 + 8 < NN){
      *(__half2*)(hout + (size_t)(row0+8)*64 + col) =
        __floats2half2_rn(fmaxf(acc[nt][2] + b0v, 0.f), fmaxf(acc[nt][3] + b1v, 0.f));
    }
  }
}

// ---------------- Set2Set ----------------
__global__ void __launch_bounds__(256) k_gates(){
  __shared__ float Asg[64][36];
  __shared__ float Bsg[32][64];
  int tid = threadIdx.x;
  int tx = tid & 15, ty = tid >> 4;
  int m0 = blockIdx.x * 64;
  int n0 = blockIdx.y * 64;
  int lrow = tid >> 2;
  int lk = (tid & 3) * 8;
  int grow = m0 + lrow;
  int bk = tid >> 3, be = (tid & 7) * 8;
  float acc[4][4] = {};
  for (int kk = 0; kk < 6; kk++){
    int kb = kk * 32;
    float4 a0, a1;
    if (kk < 4){
      const float* p = g_qstar + grow*128 + kb + lk;
      a0 = *(const float4*)p; a1 = *(const float4*)(p+4);
    } else {
      const float* p = g_hx + grow*64 + (kb - 128) + lk;
      a0 = *(const float4*)p; a1 = *(const float4*)(p+4);
    }
    const float* wp = g_Wl + (kb + bk)*256 + n0 + be;
    float4 b0 = *(const float4*)wp;
    float4 b1 = *(const float4*)(wp+4);
    __syncthreads();
    *(float4*)&Asg[lrow][lk]   = a0;
    *(float4*)&Asg[lrow][lk+4] = a1;
    *(float4*)&Bsg[bk][be]     = b0;
    *(float4*)&Bsg[bk][be+4]   = b1;
    __syncthreads();
    #pragma unroll
    for (int k = 0; k < 32; k++){
      float4 bv = *(float4*)&Bsg[k][tx*4];
      #pragma unroll
      for (int i = 0; i < 4; i++){
        float av = Asg[ty*4+i][k];
        acc[i][0] += av*bv.x;
        acc[i][1] += av*bv.y;
        acc[i][2] += av*bv.z;
        acc[i][3] += av*bv.w;
      }
    }
  }
  #pragma unroll
  for (int i = 0; i < 4; i++){
    int m = m0 + ty*4 + i;
    float* op = g_gates + m*256 + n0 + tx*4;
    op[0] = acc[i][0] + g_bl[n0 + tx*4 + 0];
    op[1] = acc[i][1] + g_bl[n0 + tx*4 + 1];
    op[2] = acc[i][2] + g_bl[n0 + tx*4 + 2];
    op[3] = acc[i][3] + g_bl[n0 + tx*4 + 3];
  }
}

__device__ __forceinline__ float sigf(float v){ return 1.0f/(1.0f + expf(-v)); }

// fused LSTM update + softmax readout over fp16 h. Block per graph, 128 threads.
__global__ void __launch_bounds__(128) k_read(const __half* __restrict__ h){
  __shared__ float se[CAP];
  __shared__ float shx[64];
  __shared__ float red[2];
  int g = blockIdx.x;
  int tid = threadIdx.x, lane = tid & 31, w = tid >> 5;
  int s0 = g_gstart[g];
  int cnt = g_gstart[g+1] - s0;
  if (cnt > CAP) cnt = CAP;
  // LSTM update (threads 0..63)
  if (tid < 64){
    const float* ga = g_gates + g*256;
    float iv = sigf(ga[tid]);
    float fv = sigf(ga[64+tid]);
    float gv = tanhf(ga[128+tid]);
    float ov = sigf(ga[192+tid]);
    float c = fv * g_cx[g*64+tid] + iv * gv;
    float hx = ov * tanhf(c);
    g_cx[g*64+tid] = c;
    g_hx[g*64+tid] = hx;
    shx[tid] = hx;
  }
  __syncthreads();
  // e per node (lane handles dims {2*lane, 2*lane+1})
  for (int i = w; i < cnt; i += 4){
    const __half2* hr = (const __half2*)(h + (size_t)(s0+i)*64);
    float2 f = __half22float2(hr[lane]);
    float s = f.x*shx[2*lane] + f.y*shx[2*lane+1];
    #pragma unroll
    for (int o = 16; o; o >>= 1) s += __shfl_xor_sync(0xffffffffu, s, o);
    if (lane == 0) se[i] = s;
  }
  __syncthreads();
  if (tid < 32){
    float m = -3.0e38f;
    for (int i = lane; i < cnt; i += 32) m = fmaxf(m, se[i]);
    #pragma unroll
    for (int o = 16; o; o >>= 1) m = fmaxf(m, __shfl_xor_sync(0xffffffffu, m, o));
    if (lane == 0) red[0] = m;
  }
  __syncthreads();
  float m = red[0];
  for (int i = tid; i < cnt; i += 128) se[i] = expf(se[i] - m);
  __syncthreads();
  if (tid < 32){
    float s = 0.f;
    for (int i = lane; i < cnt; i += 32) s += se[i];
    #pragma unroll
    for (int o = 16; o; o >>= 1) s += __shfl_xor_sync(0xffffffffu, s, o);
    if (lane == 0) red[1] = s;
  }
  __syncthreads();
  float ssum = red[1];
  if (tid < 64){
    float r = 0.f;
    #pragma unroll 4
    for (int i = 0; i < cnt; i++) r += se[i] * __half2float(h[(size_t)(s0+i)*64 + tid]);
    g_qstar[g*128 + tid]      = shx[tid];
    g_qstar[g*128 + 64 + tid] = (ssum > 0.f) ? (r / ssum) : 0.f;
  }
}

// ---------------- head ----------------
__global__ void k_lin1(const float* __restrict__ w, const float* __restrict__ b){
  int t = blockIdx.x*blockDim.x + threadIdx.x;
  if (t >= NG*64) return;
  int g = t >> 6, e = t & 63;
  float s = b[e];
  const float* q = g_qstar + g*128;
  #pragma unroll 8
  for (int k = 0; k < 128; k++) s += q[k]*w[k*64+e];
  g_out1[t] = fmaxf(s, 0.f);
}

__global__ void k_lin2(const float* __restrict__ w, const float* __restrict__ b,
                       float* __restrict__ out){
  int t = blockIdx.x*blockDim.x + threadIdx.x;
  if (t >= NG*12) return;
  int g = t / 12, j = t % 12;
  float s = b[j];
  const float* o1 = g_out1 + g*64;
  #pragma unroll 8
  for (int d = 0; d < 64; d++) s += o1[d]*w[d*12+j];
  out[t] = s;
}

// ---------------- launch ----------------
extern "C" void kernel_launch(void* const* d_in, const int* in_sizes, int n_in,
                              void* d_out, int out_size){
  const float* x      = (const float*)d_in[0];
  const int*   ei     = (const int*)  d_in[1];
  const int*   et     = (const int*)  d_in[2];
  const int*   batch  = (const int*)  d_in[3];
  const float* lin0_w = (const float*)d_in[4];
  const float* lin0_b = (const float*)d_in[5];
  const float* basis  = (const float*)d_in[6];
  const float* att    = (const float*)d_in[7];
  const float* root   = (const float*)d_in[8];
  const float* conv_b = (const float*)d_in[9];
  const float* w_ih   = (const float*)d_in[10];
  const float* w_hh   = (const float*)d_in[11];
  const float* b_ih   = (const float*)d_in[12];
  const float* b_hh   = (const float*)d_in[13];
  const float* lin1_w = (const float*)d_in[14];
  const float* lin1_b = (const float*)d_in[15];
  const float* lin2_w = (const float*)d_in[16];
  const float* lin2_b = (const float*)d_in[17];
  float* out = (float*)d_out;

  void *p_cnt=0, *p_fill=0, *p_qs=0, *p_hx=0, *p_cx=0, *p_h=0, *p_h2=0;
  cudaGetSymbolAddress(&p_cnt,  g_cnt);
  cudaGetSymbolAddress(&p_fill, g_fill);
  cudaGetSymbolAddress(&p_qs,   g_qstar);
  cudaGetSymbolAddress(&p_hx,   g_hx);
  cudaGetSymbolAddress(&p_cx,   g_cx);
  cudaGetSymbolAddress(&p_h,    g_hh);
  cudaGetSymbolAddress(&p_h2,   g_hh2);

  // prologue: weights, h0, CSR build, graph offsets
  k_wc<<<384, 64>>>(att, basis, root);
  k_wb<<<384, 64>>>();
  k_h0<<<(NN+3)/4, 256>>>(x, lin0_w, lin0_b);
  cudaMemsetAsync(p_cnt, 0, NN*sizeof(int));
  cudaMemsetAsync(p_fill, 0, NN*sizeof(int));
  k_hist<<<(NE+255)/256, 256>>>(ei + NE);
  k_scan1<<<NB, 512>>>();
  k_scan2<<<1, 32>>>();
  k_scan3<<<NB, 512>>>();
  k_scatter<<<(NE+255)/256, 256>>>(ei, et);
  k_invc<<<(NN+255)/256, 256>>>();
  k_gstart<<<(NG+256)/256, 256>>>(batch);
  k_wl<<<192, 256>>>(w_ih, w_hh, b_ih, b_hh);
  cudaMemsetAsync(p_qs, 0, NG*128*sizeof(float));
  cudaMemsetAsync(p_hx, 0, NG*64*sizeof(float));
  cudaMemsetAsync(p_cx, 0, NG*64*sizeof(float));

  // RGCN propagation: CSR aggregate -> fp16 panel -> pipelined fp16 tensor GEMM
  __half* hA = (__half*)p_h;
  __half* hB = (__half*)p_h2;
  for (int s = 0; s < 6; s++){
    k_agg<<<NN/8, 256>>>(hA);
    k_gemm<<<NNP/128, 256>>>(hA, hB, conv_b);
    __half* tmp = hA; hA = hB; hB = tmp;
  }

  // Set2Set: gates GEMM + fused(update, softmax readout)
  for (int t = 0; t < 6; t++){
    k_gates<<<dim3(NG/64, 4), 256>>>();
    k_read<<<NG, 128>>>(hA);
  }

  // head
  k_lin1<<<(NG*64+255)/256, 256>>>(lin1_w, lin1_b);
  k_lin2<<<(NG*12+255)/256, 256>>>(lin2_w, lin2_b, out);
}